// round 1
// baseline (speedup 1.0000x reference)
#include <cuda_runtime.h>

// Problem constants (fixed by the reference setup_inputs)
#define NB 32    // batch
#define NT 256   // time steps
#define NN 100   // nodes
#define ND 128   // feature dim D
#define NE 5     // experts
#define NP 768   // prior emb dim
#define NH 256   // prior MLP hidden
#define NI 257   // 2D+1 combined input dim

// Scratch (static device globals; no runtime allocation)
__device__ float g_vv[NN * NE];                 // per-node expert weights [N,E]
__device__ float g_Weff[3 * NN * NI * ND];      // effective gate weights [3,N,257,128] (input-permuted)
__device__ float g_beff[3 * NN * ND];           // effective gate biases  [3,N,128]
__device__ float g_vt[NB * NN];                 // var_total [B,N]

// ---------------------------------------------------------------------------
// vv_n = relu(prior @ W_ps1 + b_ps1) @ W_ps2 + b_ps2      [N,E]
// one CTA per node, 256 threads (== NH)
// ---------------------------------------------------------------------------
__global__ void k_vv(const float* __restrict__ prior, const float* __restrict__ W1,
                     const float* __restrict__ b1, const float* __restrict__ W2,
                     const float* __restrict__ b2) {
    __shared__ float hid[NH];
    int n = blockIdx.x, j = threadIdx.x;
    float acc = b1[j];
    const float* pr = prior + n * NP;
    #pragma unroll 8
    for (int p = 0; p < NP; ++p) acc = fmaf(pr[p], W1[p * NH + j], acc);
    hid[j] = fmaxf(acc, 0.0f);
    __syncthreads();
    if (j < NE) {
        float a2 = b2[j];
        for (int k = 0; k < NH; ++k) a2 = fmaf(hid[k], W2[k * NE + j], a2);
        g_vv[n * NE + j] = a2;
    }
}

// ---------------------------------------------------------------------------
// W_eff[g,n,i',o] = sum_e vv[n,e] * W_g[e, src(i'), o]
// input index permutation: i' in [0,128) -> h (src 129+i'),
//                          i' in [128,256) -> obs (src i'-128),
//                          i' == 256 -> rarity (src 128)
// so the scan kernel's shared "combined" buffer is float4-aligned everywhere.
// ---------------------------------------------------------------------------
__global__ void k_weff(const float* __restrict__ Wr, const float* __restrict__ Wu,
                       const float* __restrict__ Wc) {
    int idx = blockIdx.x * blockDim.x + threadIdx.x;
    const int total = 3 * NN * NI * ND;
    if (idx >= total) return;
    int o = idx & (ND - 1);
    int r = idx / ND;
    int ip = r % NI; r /= NI;
    int n = r % NN;
    int g = r / NN;
    int src_i = (ip < 128) ? (ip + 129) : ((ip < 256) ? (ip - 128) : 128);
    const float* W = (g == 0) ? Wr : ((g == 1) ? Wu : Wc);
    const float* vv = g_vv + n * NE;
    float acc = 0.0f;
    #pragma unroll
    for (int e = 0; e < NE; ++e)
        acc = fmaf(vv[e], W[(e * NI + src_i) * ND + o], acc);
    g_Weff[idx] = acc;
}

__global__ void k_beff(const float* __restrict__ br, const float* __restrict__ bu,
                       const float* __restrict__ bc) {
    int idx = blockIdx.x * blockDim.x + threadIdx.x;
    if (idx >= 3 * NN * ND) return;
    int o = idx & (ND - 1);
    int n = (idx / ND) % NN;
    int g = idx / (ND * NN);
    const float* bs = (g == 0) ? br : ((g == 1) ? bu : bc);
    const float* vv = g_vv + n * NE;
    float acc = 0.0f;
    #pragma unroll
    for (int e = 0; e < NE; ++e)
        acc = fmaf(vv[e], bs[e * ND + o], acc);
    g_beff[idx] = acc;
}

// var_total[b,n] = sum_t mask[b,t,n]
__global__ void k_vt(const int* __restrict__ mask) {
    int tid = blockIdx.x * blockDim.x + threadIdx.x;
    if (tid >= NB * NN) return;
    int b = tid / NN, n = tid % NN;
    int s = 0;
    for (int t = 0; t < NT; ++t) s += mask[(b * NT + t) * NN + n];
    g_vt[tid] = (float)s;
}

// ---------------------------------------------------------------------------
// Persistent scan: each warp owns one (b,n) pair for the whole sequence.
// h stays in registers (float4 per lane, 4 outputs each).
// Grid (NN, 2) x 512 threads: 16 warps/CTA = 16 batches of one node,
// kept lockstep with __syncthreads so weight streams share L1.
// Skips: mask==0 steps (h unchanged) and t > end_step[b] (never observable).
// ---------------------------------------------------------------------------
__global__ void __launch_bounds__(512, 2) k_scan(
    const float* __restrict__ obs, const int* __restrict__ mask,
    const int* __restrict__ lengths, const float* __restrict__ avg,
    float* __restrict__ out)
{
    __shared__ float comb[16][NI + 3];   // per-warp combined buffer [h | obs | rarity]
    __shared__ int s_maxend;

    const int n    = blockIdx.x;
    const int w    = threadIdx.x >> 5;
    const int lane = threadIdx.x & 31;
    const int b    = blockIdx.y * 16 + w;
    const int o    = lane << 2;
    const int end  = lengths[b] - 1;

    if (threadIdx.x == 0) s_maxend = 0;
    __syncthreads();
    if (lane == 0) atomicMax(&s_maxend, end);
    __syncthreads();
    const int maxend = s_maxend;

    const float* Wr = g_Weff + (0 * NN + n) * (NI * ND);
    const float* Wu = g_Weff + (1 * NN + n) * (NI * ND);
    const float* Wc = g_Weff + (2 * NN + n) * (NI * ND);
    const float4 br4 = *(const float4*)(g_beff + (0 * NN + n) * ND + o);
    const float4 bu4 = *(const float4*)(g_beff + (1 * NN + n) * ND + o);
    const float4 bc4 = *(const float4*)(g_beff + (2 * NN + n) * ND + o);
    const float vt1 = g_vt[b * NN + n] + 1.0f;
    float* cb = comb[w];

    float4 h4 = make_float4(0.f, 0.f, 0.f, 0.f);

    for (int t = 0; t <= maxend; ++t) {
        const int bt = (b * NT + t) * NN + n;
        bool act = false;
        if (t <= end) act = (mask[bt] > 0);
        if (act) {
            // Build combined: [h(0:128) | obs(128:256) | rarity(256)]
            *(float4*)&cb[128 + o] = *(const float4*)(obs + bt * ND + o);
            if (lane == 0) cb[256] = 0.5f * tanhf(avg[bt] / vt1);
            *(float4*)&cb[o] = h4;
            __syncwarp();

            // r and u gates (shared input loop)
            float4 ar = br4, au = bu4;
            #pragma unroll 2
            for (int i = 0; i < NI; ++i) {
                const float ci = cb[i];
                const float4 w1 = *(const float4*)(Wr + i * ND + o);
                const float4 w2 = *(const float4*)(Wu + i * ND + o);
                ar.x = fmaf(ci, w1.x, ar.x); ar.y = fmaf(ci, w1.y, ar.y);
                ar.z = fmaf(ci, w1.z, ar.z); ar.w = fmaf(ci, w1.w, ar.w);
                au.x = fmaf(ci, w2.x, au.x); au.y = fmaf(ci, w2.y, au.y);
                au.z = fmaf(ci, w2.z, au.z); au.w = fmaf(ci, w2.w, au.w);
            }
            float4 rr, uu, hr;
            rr.x = 1.f / (1.f + expf(-ar.x)); rr.y = 1.f / (1.f + expf(-ar.y));
            rr.z = 1.f / (1.f + expf(-ar.z)); rr.w = 1.f / (1.f + expf(-ar.w));
            uu.x = 1.f / (1.f + expf(-au.x)); uu.y = 1.f / (1.f + expf(-au.y));
            uu.z = 1.f / (1.f + expf(-au.z)); uu.w = 1.f / (1.f + expf(-au.w));
            hr.x = rr.x * h4.x; hr.y = rr.y * h4.y;
            hr.z = rr.z * h4.z; hr.w = rr.w * h4.w;

            // swap in h_reset
            __syncwarp();
            *(float4*)&cb[o] = hr;
            __syncwarp();

            // c gate
            float4 ac = bc4;
            #pragma unroll 4
            for (int i = 0; i < NI; ++i) {
                const float ci = cb[i];
                const float4 w3 = *(const float4*)(Wc + i * ND + o);
                ac.x = fmaf(ci, w3.x, ac.x); ac.y = fmaf(ci, w3.y, ac.y);
                ac.z = fmaf(ci, w3.z, ac.z); ac.w = fmaf(ci, w3.w, ac.w);
            }
            float4 cc;
            cc.x = tanhf(ac.x); cc.y = tanhf(ac.y);
            cc.z = tanhf(ac.z); cc.w = tanhf(ac.w);

            // h = (1-u)*h_reset + u*c = h_reset + u*(c - h_reset)
            h4.x = fmaf(uu.x, cc.x - hr.x, hr.x);
            h4.y = fmaf(uu.y, cc.y - hr.y, hr.y);
            h4.z = fmaf(uu.z, cc.z - hr.z, hr.z);
            h4.w = fmaf(uu.w, cc.w - hr.w, hr.w);

            __syncwarp();
        }
        if (t == end) {
            *(float4*)(out + (b * NN + n) * ND + o) = h4;
        }
        __syncthreads();  // keep warps lockstep so weight streams share L1
    }
}

// ---------------------------------------------------------------------------
extern "C" void kernel_launch(void* const* d_in, const int* in_sizes, int n_in,
                              void* d_out, int out_size) {
    const float* obs   = (const float*)d_in[0];   // obs_emb [B,T,N,D]
    // d_in[1] adj, d_in[3] observed_tp, d_in[4] tp_emb_tensor: unused by the math
    const int*   msk   = (const int*)d_in[2];     // observed_mask [B,T,N]
    const int*   lens  = (const int*)d_in[5];     // lengths [B,1]
    const float* avg   = (const float*)d_in[6];   // avg_interval [B,T,N]
    const float* prior = (const float*)d_in[7];   // var_prior_emb [N,P]
    const float* Wr = (const float*)d_in[8];
    const float* br = (const float*)d_in[9];
    const float* Wu = (const float*)d_in[10];
    const float* bu = (const float*)d_in[11];
    const float* Wc = (const float*)d_in[12];
    const float* bc = (const float*)d_in[13];
    const float* W1 = (const float*)d_in[14];
    const float* b1 = (const float*)d_in[15];
    const float* W2 = (const float*)d_in[16];
    const float* b2 = (const float*)d_in[17];
    float* out = (float*)d_out;

    k_vv<<<NN, NH>>>(prior, W1, b1, W2, b2);

    const int totalW = 3 * NN * NI * ND;
    k_weff<<<(totalW + 255) / 256, 256>>>(Wr, Wu, Wc);
    k_beff<<<(3 * NN * ND + 255) / 256, 256>>>(br, bu, bc);
    k_vt<<<(NB * NN + 255) / 256, 256>>>(msk);

    k_scan<<<dim3(NN, 2), 512>>>(obs, msk, lens, avg, out);
}

// round 3
// speedup vs baseline: 1.8873x; 1.8873x over previous
#include <cuda_runtime.h>

#define NB 32    // batch
#define NT 256   // time steps
#define NN 100   // nodes
#define ND 128   // feature dim D
#define NE 5     // experts
#define NP 768   // prior emb dim
#define NHID 256 // prior MLP hidden
#define NC 384   // 3 gates * 128 output cols (r|u|c)

typedef unsigned long long u64;

// -------- static device scratch (no runtime allocation) --------
__device__ float g_vv[NN * NE];                    // [N,E]
__device__ float g_vt[NB * NN];                    // var_total [B,N]
__device__ float g_beff[NN * NC];                  // effective biases [N,384]
__device__ float g_Wx[NN * 129 * NC];              // x-part weights  [N,129,384]
__device__ float g_Wh[NN * 128 * NC];              // h-part weights  [N,128,384]
__device__ float g_gx[NN * NB * NT * NC];          // precomputed x-contribs (1.26GB)

// -------- packed f32x2 helpers --------
__device__ __forceinline__ u64 pk2(float v) {
    u64 r; unsigned u = __float_as_uint(v);
    asm("mov.b64 %0, {%1, %1};" : "=l"(r) : "r"(u));
    return r;
}
__device__ __forceinline__ void fma2(u64& d, u64 a, u64 b) {
    asm("fma.rn.f32x2 %0, %1, %2, %0;" : "+l"(d) : "l"(a), "l"(b));
}
__device__ __forceinline__ float2 up2(u64 p) {
    unsigned lo, hi;
    asm("mov.b64 {%0, %1}, %2;" : "=r"(lo), "=r"(hi) : "l"(p));
    return make_float2(__uint_as_float(lo), __uint_as_float(hi));
}
__device__ __forceinline__ float sigm(float x) { return 1.0f / (1.0f + expf(-x)); }

// ---------------------------------------------------------------------------
// vv_n = relu(prior @ W_ps1 + b_ps1) @ W_ps2 + b_ps2   [N,E]
// ---------------------------------------------------------------------------
__global__ void k_vv(const float* __restrict__ prior, const float* __restrict__ W1,
                     const float* __restrict__ b1, const float* __restrict__ W2,
                     const float* __restrict__ b2) {
    __shared__ float hid[NHID];
    int n = blockIdx.x, j = threadIdx.x;
    float acc = b1[j];
    const float* pr = prior + n * NP;
    #pragma unroll 8
    for (int p = 0; p < NP; ++p) acc = fmaf(pr[p], W1[p * NHID + j], acc);
    hid[j] = fmaxf(acc, 0.0f);
    __syncthreads();
    if (j < NE) {
        float a2 = b2[j];
        for (int k = 0; k < NHID; ++k) a2 = fmaf(hid[k], W2[k * NE + j], a2);
        g_vv[n * NE + j] = a2;
    }
}

// var_total[b,n] = sum_t mask[b,t,n]
__global__ void k_vt(const int* __restrict__ mask) {
    int tid = blockIdx.x * blockDim.x + threadIdx.x;
    if (tid >= NB * NN) return;
    int b = tid / NN, n = tid % NN;
    int s = 0;
    for (int t = 0; t < NT; ++t) s += mask[(b * NT + t) * NN + n];
    g_vt[tid] = (float)s;
}

// ---------------------------------------------------------------------------
// Effective weights: Wx[n,k,g*128+o] = sum_e vv[n,e]*W_g[e,k,o]  (k<129: x rows)
//                    Wh[n,k,..]      = rows 129..256 (h part)
//                    beff[n,g*128+o] = sum_e vv[n,e]*b_g[e,o]
// ---------------------------------------------------------------------------
__global__ void k_weff(const float* __restrict__ Wr, const float* __restrict__ Wu,
                       const float* __restrict__ Wc,
                       const float* __restrict__ br, const float* __restrict__ bu,
                       const float* __restrict__ bc) {
    int idx = blockIdx.x * blockDim.x + threadIdx.x;
    const int total = NN * 257 * NC;
    if (idx >= total) return;
    int col = idx % NC;
    int k   = (idx / NC) % 257;
    int n   = idx / (NC * 257);
    int g = col >> 7, o = col & 127;
    const float* W = (g == 0) ? Wr : ((g == 1) ? Wu : Wc);
    const float* vv = g_vv + n * NE;
    float acc = 0.0f;
    #pragma unroll
    for (int e = 0; e < NE; ++e)
        acc = fmaf(vv[e], W[(e * 257 + k) * ND + o], acc);
    if (k < 129) g_Wx[(n * 129 + k) * NC + col] = acc;
    else         g_Wh[(n * 128 + (k - 129)) * NC + col] = acc;
    if (k == 0) {
        const float* bb = (g == 0) ? br : ((g == 1) ? bu : bc);
        float ab = 0.0f;
        #pragma unroll
        for (int e = 0; e < NE; ++e) ab = fmaf(vv[e], bb[e * ND + o], ab);
        g_beff[n * NC + col] = ab;
    }
}

// ---------------------------------------------------------------------------
// gx[n,b,t,0:384] = [obs(b,t,n,:), rarity] @ Wx[n] + beff[n]   for t <= end[b]
// CTA per (b,n); 384 threads = 96 col-groups (4 cols) x 4 row-groups (8 rows).
// ---------------------------------------------------------------------------
__global__ void __launch_bounds__(384) k_gx(const float* __restrict__ obs,
                                            const float* __restrict__ avg,
                                            const int* __restrict__ lengths) {
    const int b = blockIdx.x, n = blockIdx.y;
    const int tid = threadIdx.x;
    const int cg = tid % 96;       // column group
    const int rg = tid / 96;       // row group 0..3
    const int c4 = cg * 4;
    const int end = lengths[b] - 1;
    const float vt1 = g_vt[b * NN + n] + 1.0f;
    const float* Wx = g_Wx + n * (129 * NC);
    __shared__ u64 xs2[32][132];   // packed-duplicated x rows [t-row][k]

    u64 bias0, bias1;
    { ulonglong2 bv = *(const ulonglong2*)(g_beff + n * NC + c4);
      bias0 = bv.x; bias1 = bv.y; }

    for (int t0 = 0; t0 <= end; t0 += 32) {
        const int rows = min(32, end + 1 - t0);
        __syncthreads();
        for (int i = tid; i < (rows << 7); i += 384) {
            int r = i >> 7, c = i & 127;
            xs2[r][c] = pk2(obs[(((b * NT + t0 + r) * NN) + n) * ND + c]);
        }
        if (tid < rows)
            xs2[tid][128] = pk2(0.5f * tanhf(avg[(b * NT + t0 + tid) * NN + n] / vt1));
        __syncthreads();

        u64 acc[8][2];
        #pragma unroll
        for (int r = 0; r < 8; ++r) { acc[r][0] = bias0; acc[r][1] = bias1; }

        #pragma unroll 1
        for (int k = 0; k < 129; ++k) {
            ulonglong2 w = *(const ulonglong2*)(Wx + k * NC + c4);
            #pragma unroll
            for (int r = 0; r < 8; ++r) {
                u64 xv = xs2[rg * 8 + r][k];
                fma2(acc[r][0], xv, w.x);
                fma2(acc[r][1], xv, w.y);
            }
        }
        #pragma unroll
        for (int r = 0; r < 8; ++r) {
            int row = rg * 8 + r;
            if (row < rows) {
                ulonglong2 st; st.x = acc[r][0]; st.y = acc[r][1];
                *(ulonglong2*)(g_gx + (((n * NB + b) * NT) + t0 + row) * NC + c4) = st;
            }
        }
    }
}

// ---------------------------------------------------------------------------
// Scan: CTA per node, 8 warps x 4 batches each; h in registers + one packed
// smem mirror (h2, 32KB) that is overwritten in-place with h_reset for the
// c-gate (the r/u gates are done with h by then). K=128 (h part only);
// gx supplies x-part + bias. No CTA-level barriers: warps run free.
// ---------------------------------------------------------------------------
__global__ void __launch_bounds__(256, 1) k_scan(const int* __restrict__ mask,
                                                 const int* __restrict__ lengths,
                                                 float* __restrict__ out) {
    const int n  = blockIdx.x;
    const int w  = threadIdx.x >> 5;
    const int l  = threadIdx.x & 31;
    const int c4 = l << 2;
    const int b0 = w << 2;
    __shared__ u64 h2[NB][128];    // packed-duplicated h (then h_reset) [batch][k]

    int endq[4]; int wmax = 0;
    #pragma unroll
    for (int q = 0; q < 4; ++q) {
        endq[q] = lengths[b0 + q] - 1;
        if (endq[q] > wmax) wmax = endq[q];
    }
    // per-lane end for the ballot (avoid dynamic register-array index)
    const int myend = lengths[b0 + (l & 3)] - 1;

    float4 h4[4];
    #pragma unroll
    for (int q = 0; q < 4; ++q) {
        h4[q] = make_float4(0.f, 0.f, 0.f, 0.f);
        #pragma unroll
        for (int j = 0; j < 4; ++j) h2[b0 + q][c4 + j] = 0ull;
    }
    __syncwarp();

    const float* Wh  = g_Wh + n * (128 * NC);
    const float* gx0 = g_gx + ((n * NB + b0) * NT) * NC;

    for (int t = 0; t <= wmax; ++t) {
        int a = 0;
        if (l < 4) a = (t <= myend) && (mask[((b0 + l) * NT + t) * NN + n] > 0);
        unsigned am = __ballot_sync(0xffffffffu, a) & 0xFu;

        if (am) {
            const float* gxt = gx0 + t * NC;
            u64 ar[4][2], au[4][2];
            #pragma unroll
            for (int q = 0; q < 4; ++q) {
                const float* gx = gxt + q * (NT * NC);
                ulonglong2 r0 = *(const ulonglong2*)(gx + c4);
                ulonglong2 u0 = *(const ulonglong2*)(gx + 128 + c4);
                ar[q][0] = r0.x; ar[q][1] = r0.y;
                au[q][0] = u0.x; au[q][1] = u0.y;
            }
            #pragma unroll 2
            for (int k = 0; k < 128; ++k) {
                ulonglong2 wr = *(const ulonglong2*)(Wh + k * NC + c4);
                ulonglong2 wu = *(const ulonglong2*)(Wh + k * NC + 128 + c4);
                #pragma unroll
                for (int q = 0; q < 4; ++q) {
                    u64 hv = h2[b0 + q][k];
                    fma2(ar[q][0], hv, wr.x); fma2(ar[q][1], hv, wr.y);
                    fma2(au[q][0], hv, wu.x); fma2(au[q][1], hv, wu.y);
                }
            }
            float4 uu[4], hr4[4];
            #pragma unroll
            for (int q = 0; q < 4; ++q) {
                float2 a0 = up2(ar[q][0]), a1 = up2(ar[q][1]);
                float2 u0 = up2(au[q][0]), u1 = up2(au[q][1]);
                float4 rr;
                rr.x = sigm(a0.x); rr.y = sigm(a0.y); rr.z = sigm(a1.x); rr.w = sigm(a1.y);
                uu[q].x = sigm(u0.x); uu[q].y = sigm(u0.y);
                uu[q].z = sigm(u1.x); uu[q].w = sigm(u1.y);
                hr4[q].x = rr.x * h4[q].x; hr4[q].y = rr.y * h4[q].y;
                hr4[q].z = rr.z * h4[q].z; hr4[q].w = rr.w * h4[q].w;
                if (am & (1u << q)) {   // overwrite h with h_reset (inactive keep h)
                    h2[b0 + q][c4 + 0] = pk2(hr4[q].x);
                    h2[b0 + q][c4 + 1] = pk2(hr4[q].y);
                    h2[b0 + q][c4 + 2] = pk2(hr4[q].z);
                    h2[b0 + q][c4 + 3] = pk2(hr4[q].w);
                }
            }
            __syncwarp();

            u64 ac[4][2];
            #pragma unroll
            for (int q = 0; q < 4; ++q) {
                ulonglong2 c0 = *(const ulonglong2*)(gxt + q * (NT * NC) + 256 + c4);
                ac[q][0] = c0.x; ac[q][1] = c0.y;
            }
            #pragma unroll 2
            for (int k = 0; k < 128; ++k) {
                ulonglong2 wc = *(const ulonglong2*)(Wh + k * NC + 256 + c4);
                #pragma unroll
                for (int q = 0; q < 4; ++q) {
                    u64 hv = h2[b0 + q][k];
                    fma2(ac[q][0], hv, wc.x); fma2(ac[q][1], hv, wc.y);
                }
            }
            __syncwarp();
            #pragma unroll
            for (int q = 0; q < 4; ++q) {
                if (am & (1u << q)) {
                    float2 c0 = up2(ac[q][0]), c1 = up2(ac[q][1]);
                    float4 cc;
                    cc.x = tanhf(c0.x); cc.y = tanhf(c0.y);
                    cc.z = tanhf(c1.x); cc.w = tanhf(c1.y);
                    h4[q].x = fmaf(uu[q].x, cc.x - hr4[q].x, hr4[q].x);
                    h4[q].y = fmaf(uu[q].y, cc.y - hr4[q].y, hr4[q].y);
                    h4[q].z = fmaf(uu[q].z, cc.z - hr4[q].z, hr4[q].z);
                    h4[q].w = fmaf(uu[q].w, cc.w - hr4[q].w, hr4[q].w);
                    h2[b0 + q][c4 + 0] = pk2(h4[q].x);
                    h2[b0 + q][c4 + 1] = pk2(h4[q].y);
                    h2[b0 + q][c4 + 2] = pk2(h4[q].z);
                    h2[b0 + q][c4 + 3] = pk2(h4[q].w);
                }
            }
            __syncwarp();
        }
        #pragma unroll
        for (int q = 0; q < 4; ++q)
            if (t == endq[q])
                *(float4*)(out + ((b0 + q) * NN + n) * ND + c4) = h4[q];
    }
}

// ---------------------------------------------------------------------------
extern "C" void kernel_launch(void* const* d_in, const int* in_sizes, int n_in,
                              void* d_out, int out_size) {
    const float* obs   = (const float*)d_in[0];   // [B,T,N,D]
    const int*   msk   = (const int*)d_in[2];     // [B,T,N]
    const int*   lens  = (const int*)d_in[5];     // [B,1]
    const float* avg   = (const float*)d_in[6];   // [B,T,N]
    const float* prior = (const float*)d_in[7];   // [N,P]
    const float* Wr = (const float*)d_in[8];
    const float* br = (const float*)d_in[9];
    const float* Wu = (const float*)d_in[10];
    const float* bu = (const float*)d_in[11];
    const float* Wc = (const float*)d_in[12];
    const float* bc = (const float*)d_in[13];
    const float* W1 = (const float*)d_in[14];
    const float* b1 = (const float*)d_in[15];
    const float* W2 = (const float*)d_in[16];
    const float* b2 = (const float*)d_in[17];
    float* out = (float*)d_out;

    k_vv<<<NN, NHID>>>(prior, W1, b1, W2, b2);
    k_vt<<<(NB * NN + 255) / 256, 256>>>(msk);
    k_weff<<<(NN * 257 * NC + 255) / 256, 256>>>(Wr, Wu, Wc, br, bu, bc);
    k_gx<<<dim3(NB, NN), 384>>>(obs, avg, lens);
    k_scan<<<NN, 256>>>(msk, lens, out);
}

// round 4
// speedup vs baseline: 2.8341x; 1.5017x over previous
#include <cuda_runtime.h>

#define NB 32    // batch
#define NT 256   // time steps
#define NN 100   // nodes
#define ND 128   // feature dim D
#define NE 5     // experts
#define NP 768   // prior emb dim
#define NHID 256 // prior MLP hidden
#define NC 384   // 3 gates * 128 output cols, interleaved: [ (r0,r1,u0,u1) x64 | c0..c127 ]

typedef unsigned long long u64;

// -------- static device scratch --------
__device__ float g_vv[NN * NE];
__device__ float g_vt[NB * NN];
__device__ float g_beff[NN * NC];            // permuted cols
__device__ float g_Wx[NN * 129 * NC];        // permuted cols
__device__ float g_Wh[NN * 128 * NC];        // permuted cols
__device__ float g_gx[NN * NB * NT * NC];    // permuted cols (1.26GB)
__device__ unsigned g_mb[NN * NT];           // per-(n,t) active-batch bitmask

// -------- packed f32x2 helpers --------
__device__ __forceinline__ u64 pk2(float v) {
    u64 r; unsigned u = __float_as_uint(v);
    asm("mov.b64 %0, {%1, %1};" : "=l"(r) : "r"(u));
    return r;
}
__device__ __forceinline__ void fma2(u64& d, u64 a, u64 b) {
    asm("fma.rn.f32x2 %0, %1, %2, %0;" : "+l"(d) : "l"(a), "l"(b));
}
__device__ __forceinline__ float2 up2(u64 p) {
    unsigned lo, hi;
    asm("mov.b64 {%0, %1}, %2;" : "=r"(lo), "=r"(hi) : "l"(p));
    return make_float2(__uint_as_float(lo), __uint_as_float(hi));
}
__device__ __forceinline__ float sigm(float x) { return 1.0f / (1.0f + expf(-x)); }

// ---------------------------------------------------------------------------
__global__ void k_vv(const float* __restrict__ prior, const float* __restrict__ W1,
                     const float* __restrict__ b1, const float* __restrict__ W2,
                     const float* __restrict__ b2) {
    __shared__ float hid[NHID];
    int n = blockIdx.x, j = threadIdx.x;
    float acc = b1[j];
    const float* pr = prior + n * NP;
    #pragma unroll 8
    for (int p = 0; p < NP; ++p) acc = fmaf(pr[p], W1[p * NHID + j], acc);
    hid[j] = fmaxf(acc, 0.0f);
    __syncthreads();
    if (j < NE) {
        float a2 = b2[j];
        for (int k = 0; k < NHID; ++k) a2 = fmaf(hid[k], W2[k * NE + j], a2);
        g_vv[n * NE + j] = a2;
    }
}

__global__ void k_vt(const int* __restrict__ mask) {
    int tid = blockIdx.x * blockDim.x + threadIdx.x;
    if (tid >= NB * NN) return;
    int b = tid / NN, n = tid % NN;
    int s = 0;
    for (int t = 0; t < NT; ++t) s += mask[(b * NT + t) * NN + n];
    g_vt[tid] = (float)s;
}

// Active-batch bitmask per (n,t): bit b set iff mask[b,t,n]>0 and t < lengths[b]
__global__ void k_mask(const int* __restrict__ mask, const int* __restrict__ lengths) {
    int idx = blockIdx.x * blockDim.x + threadIdx.x;
    if (idx >= NN * NT) return;
    int n = idx % NN, t = idx / NN;
    unsigned w = 0;
    #pragma unroll 4
    for (int b = 0; b < NB; ++b)
        if (t < __ldg(&lengths[b]) && mask[(b * NT + t) * NN + n] > 0) w |= (1u << b);
    g_mb[n * NT + t] = w;
}

// ---------------------------------------------------------------------------
// Effective weights with COLUMN PERMUTATION:
//   pcol < 256:  pcol = 4*p + s,  s>>1 = gate (0=r,1=u), o = 2*p + (s&1)
//   pcol >= 256: gate c, o = pcol-256
// Row k<129 -> Wx (x part: obs rows 0..127, rarity row 128); k>=129 -> Wh.
// ---------------------------------------------------------------------------
__global__ void k_weff(const float* __restrict__ Wr, const float* __restrict__ Wu,
                       const float* __restrict__ Wc,
                       const float* __restrict__ br, const float* __restrict__ bu,
                       const float* __restrict__ bc) {
    int idx = blockIdx.x * blockDim.x + threadIdx.x;
    const int total = NN * 257 * NC;
    if (idx >= total) return;
    int pcol = idx % NC;
    int k    = (idx / NC) % 257;
    int n    = idx / (NC * 257);
    int g, o;
    if (pcol >= 256) { g = 2; o = pcol - 256; }
    else { g = (pcol >> 1) & 1; o = ((pcol >> 2) << 1) | (pcol & 1); }
    const float* W = (g == 0) ? Wr : ((g == 1) ? Wu : Wc);
    const float* vv = g_vv + n * NE;
    float acc = 0.0f;
    #pragma unroll
    for (int e = 0; e < NE; ++e)
        acc = fmaf(vv[e], W[(e * 257 + k) * ND + o], acc);
    if (k < 129) g_Wx[(n * 129 + k) * NC + pcol] = acc;
    else         g_Wh[(n * 128 + (k - 129)) * NC + pcol] = acc;
    if (k == 0) {
        const float* bb = (g == 0) ? br : ((g == 1) ? bu : bc);
        float ab = 0.0f;
        #pragma unroll
        for (int e = 0; e < NE; ++e) ab = fmaf(vv[e], bb[e * ND + o], ab);
        g_beff[n * NC + pcol] = ab;
    }
}

// ---------------------------------------------------------------------------
// gx[n,b,t,:] = [obs, rarity] @ Wx[n] + beff[n]   (permuted cols, t < lengths[b])
// ---------------------------------------------------------------------------
__global__ void __launch_bounds__(384) k_gx(const float* __restrict__ obs,
                                            const float* __restrict__ avg,
                                            const int* __restrict__ lengths) {
    const int b = blockIdx.x, n = blockIdx.y;
    const int tid = threadIdx.x;
    const int cg = tid % 96;
    const int rg = tid / 96;
    const int c4 = cg * 4;
    const int end = lengths[b] - 1;
    const float vt1 = g_vt[b * NN + n] + 1.0f;
    const float* Wx = g_Wx + n * (129 * NC);
    __shared__ u64 xs2[32][132];

    u64 bias0, bias1;
    { ulonglong2 bv = *(const ulonglong2*)(g_beff + n * NC + c4);
      bias0 = bv.x; bias1 = bv.y; }

    for (int t0 = 0; t0 <= end; t0 += 32) {
        const int rows = min(32, end + 1 - t0);
        __syncthreads();
        for (int i = tid; i < (rows << 7); i += 384) {
            int r = i >> 7, c = i & 127;
            xs2[r][c] = pk2(obs[(((b * NT + t0 + r) * NN) + n) * ND + c]);
        }
        if (tid < rows)
            xs2[tid][128] = pk2(0.5f * tanhf(avg[(b * NT + t0 + tid) * NN + n] / vt1));
        __syncthreads();

        u64 acc[8][2];
        #pragma unroll
        for (int r = 0; r < 8; ++r) { acc[r][0] = bias0; acc[r][1] = bias1; }

        #pragma unroll 1
        for (int k = 0; k < 129; ++k) {
            ulonglong2 w = *(const ulonglong2*)(Wx + k * NC + c4);
            #pragma unroll
            for (int r = 0; r < 8; ++r) {
                u64 xv = xs2[rg * 8 + r][k];
                fma2(acc[r][0], xv, w.x);
                fma2(acc[r][1], xv, w.y);
            }
        }
        #pragma unroll
        for (int r = 0; r < 8; ++r) {
            int row = rg * 8 + r;
            if (row < rows) {
                ulonglong2 st; st.x = acc[r][0]; st.y = acc[r][1];
                *(ulonglong2*)(g_gx + (((size_t)(n * NB + b) * NT) + t0 + row) * NC + c4) = st;
            }
        }
    }
}

// ---------------------------------------------------------------------------
// Scan step body: NBQ = max batches per group (uniform across CTA).
// thread = (group g in 0..3, col-pair ct in 0..63); owns cols (2ct,2ct+1).
// ---------------------------------------------------------------------------
template<int NBQ>
__device__ __forceinline__ void scan_step(const float* __restrict__ Wh,
                                          const float* __restrict__ gx_nt,
                                          u64* __restrict__ h2s,
                                          const int* __restrict__ s_act,
                                          int cnt, int g, int ct)
{
    int nbr = (cnt - g + 3) >> 2; if (nbr > NBQ) nbr = NBQ;
    const int nb = nbr;
    int bofs[NBQ];
    const float* gp[NBQ];
    #pragma unroll
    for (int i = 0; i < NBQ; ++i) {
        int b = s_act[(i < nb) ? (g + 4 * i) : g];   // pad slots alias slot 0
        bofs[i] = b << 7;
        gp[i] = gx_nt + (size_t)b * (NT * NC);
    }

    // ---- phase 1: r,u gates ----
    u64 ar[NBQ], au[NBQ];
    #pragma unroll
    for (int i = 0; i < NBQ; ++i) {
        ulonglong2 gv = *(const ulonglong2*)(gp[i] + 4 * ct);
        ar[i] = gv.x; au[i] = gv.y;
    }
    const float* wb = Wh + 4 * ct;
    #pragma unroll 4
    for (int k = 0; k < 128; ++k) {
        ulonglong2 w = *(const ulonglong2*)(wb + k * NC);
        #pragma unroll
        for (int i = 0; i < NBQ; ++i) {
            u64 hv = h2s[bofs[i] + k];
            fma2(ar[i], hv, w.x);
            fma2(au[i], hv, w.y);
        }
    }
    float hr0[NBQ], hr1[NBQ], uu0[NBQ], uu1[NBQ];
    #pragma unroll
    for (int i = 0; i < NBQ; ++i) {
        float2 a = up2(ar[i]), uv = up2(au[i]);
        float r0 = sigm(a.x), r1 = sigm(a.y);
        uu0[i] = sigm(uv.x); uu1[i] = sigm(uv.y);
        float h0 = ((const float*)(h2s + bofs[i] + 2 * ct))[0];
        float h1 = ((const float*)(h2s + bofs[i] + 2 * ct + 1))[0];
        hr0[i] = r0 * h0; hr1[i] = r1 * h1;
    }
    __syncthreads();                       // all phase-1 h reads done
    #pragma unroll
    for (int i = 0; i < NBQ; ++i) if (i < nb) {
        h2s[bofs[i] + 2 * ct]     = pk2(hr0[i]);
        h2s[bofs[i] + 2 * ct + 1] = pk2(hr1[i]);
    }
    __syncthreads();                       // h_reset visible

    // ---- phase 2: c gate ----
    u64 ac[NBQ];
    #pragma unroll
    for (int i = 0; i < NBQ; ++i)
        ac[i] = *(const u64*)(gp[i] + 256 + 2 * ct);
    const float* wc = Wh + 256 + 2 * ct;
    #pragma unroll 4
    for (int k = 0; k < 128; ++k) {
        u64 w = *(const u64*)(wc + k * NC);
        #pragma unroll
        for (int i = 0; i < NBQ; ++i)
            fma2(ac[i], h2s[bofs[i] + k], w);
    }
    __syncthreads();                       // all phase-2 h_reset reads done
    #pragma unroll
    for (int i = 0; i < NBQ; ++i) if (i < nb) {
        float2 c = up2(ac[i]);
        float c0 = tanhf(c.x), c1 = tanhf(c.y);
        float h0 = fmaf(uu0[i], c0 - hr0[i], hr0[i]);
        float h1 = fmaf(uu1[i], c1 - hr1[i], hr1[i]);
        h2s[bofs[i] + 2 * ct]     = pk2(h0);
        h2s[bofs[i] + 2 * ct + 1] = pk2(h1);
    }
}

__global__ void __launch_bounds__(256) k_scan(const int* __restrict__ lengths,
                                              float* __restrict__ out) {
    const int n   = blockIdx.x;
    const int tid = threadIdx.x;
    const int g   = tid >> 6;
    const int ct  = tid & 63;
    __shared__ u64 h2s[NB * 128];          // 32KB duplicated h
    __shared__ int s_act[NB];
    __shared__ int s_tmax;

    for (int j = tid; j < NB * 128; j += 256) h2s[j] = 0ull;
    if (tid == 0) {
        int m = 0;
        for (int b = 0; b < NB; ++b) { int e = lengths[b] - 1; if (e > m) m = e; }
        s_tmax = m;
    }
    __syncthreads();
    const int tmax = s_tmax;

    const float* Wh  = g_Wh + (size_t)n * (128 * NC);
    const float* gxn = g_gx + (size_t)n * NB * NT * NC;
    const unsigned* mw = g_mb + n * NT;

    for (int t = 0; t <= tmax; ++t) {
        unsigned word = mw[t];
        if (word == 0) continue;
        __syncthreads();                   // prior h writes / s_act uses done
        if (tid < 32 && ((word >> tid) & 1u))
            s_act[__popc(word & ((1u << tid) - 1u))] = tid;
        __syncthreads();
        int cnt = __popc(word);
        const float* gx_nt = gxn + (size_t)t * NC;
        switch ((cnt + 3) >> 2) {
            case 1: scan_step<1>(Wh, gx_nt, h2s, s_act, cnt, g, ct); break;
            case 2: scan_step<2>(Wh, gx_nt, h2s, s_act, cnt, g, ct); break;
            case 3: scan_step<3>(Wh, gx_nt, h2s, s_act, cnt, g, ct); break;
            case 4: scan_step<4>(Wh, gx_nt, h2s, s_act, cnt, g, ct); break;
            case 5: scan_step<5>(Wh, gx_nt, h2s, s_act, cnt, g, ct); break;
            case 6: scan_step<6>(Wh, gx_nt, h2s, s_act, cnt, g, ct); break;
            case 7: scan_step<7>(Wh, gx_nt, h2s, s_act, cnt, g, ct); break;
            default: scan_step<8>(Wh, gx_nt, h2s, s_act, cnt, g, ct); break;
        }
    }
    __syncthreads();
    // h[b] is frozen after t=end[b]; write all outputs once.
    for (int j = tid; j < NB * 128; j += 256) {
        int b = j >> 7, col = j & 127;
        out[((size_t)b * NN + n) * ND + col] = ((const float*)(h2s + j))[0];
    }
}

// ---------------------------------------------------------------------------
extern "C" void kernel_launch(void* const* d_in, const int* in_sizes, int n_in,
                              void* d_out, int out_size) {
    const float* obs   = (const float*)d_in[0];
    const int*   msk   = (const int*)d_in[2];
    const int*   lens  = (const int*)d_in[5];
    const float* avg   = (const float*)d_in[6];
    const float* prior = (const float*)d_in[7];
    const float* Wr = (const float*)d_in[8];
    const float* br = (const float*)d_in[9];
    const float* Wu = (const float*)d_in[10];
    const float* bu = (const float*)d_in[11];
    const float* Wc = (const float*)d_in[12];
    const float* bc = (const float*)d_in[13];
    const float* W1 = (const float*)d_in[14];
    const float* b1 = (const float*)d_in[15];
    const float* W2 = (const float*)d_in[16];
    const float* b2 = (const float*)d_in[17];
    float* out = (float*)d_out;

    k_vv<<<NN, NHID>>>(prior, W1, b1, W2, b2);
    k_vt<<<(NB * NN + 255) / 256, 256>>>(msk);
    k_mask<<<(NN * NT + 255) / 256, 256>>>(msk, lens);
    k_weff<<<(NN * 257 * NC + 255) / 256, 256>>>(Wr, Wu, Wc, br, bu, bc);
    k_gx<<<dim3(NB, NN), 384>>>(obs, avg, lens);
    k_scan<<<NN, 256>>>(lens, out);
}

// round 5
// speedup vs baseline: 4.2224x; 1.4898x over previous
#include <cuda_runtime.h>

#define NB 32    // batch
#define NT 256   // time steps
#define NN 100   // nodes
#define ND 128   // feature dim D
#define NE 5     // experts
#define NP 768   // prior emb dim
#define NHID 256 // prior MLP hidden
#define NC 384   // 3 gates * 128 output cols, interleaved: [ (r0,r1,u0,u1) x64 | c0..c127 ]

#define WH_FLOATS (128 * NC)               // 49152 floats = 196608 B
#define SCAN_SMEM (WH_FLOATS * 4 + NB * 128 * 8)  // 196608 + 32768 = 229376 B

typedef unsigned long long u64;

// -------- static device scratch --------
__device__ float g_vv[NN * NE];
__device__ float g_vt[NB * NN];
__device__ float g_beff[NN * NC];            // permuted cols
__device__ float g_Wx[NN * 129 * NC];        // permuted cols
__device__ float g_Wh[NN * 128 * NC];        // permuted cols
__device__ float g_gx[NN * NB * NT * NC];    // permuted cols (1.26GB)
__device__ unsigned g_mb[NN * NT];           // per-(n,t) active-batch bitmask

// -------- packed f32x2 helpers --------
__device__ __forceinline__ u64 pk2(float v) {
    u64 r; unsigned u = __float_as_uint(v);
    asm("mov.b64 %0, {%1, %1};" : "=l"(r) : "r"(u));
    return r;
}
__device__ __forceinline__ void fma2(u64& d, u64 a, u64 b) {
    asm("fma.rn.f32x2 %0, %1, %2, %0;" : "+l"(d) : "l"(a), "l"(b));
}
__device__ __forceinline__ float2 up2(u64 p) {
    unsigned lo, hi;
    asm("mov.b64 {%0, %1}, %2;" : "=r"(lo), "=r"(hi) : "l"(p));
    return make_float2(__uint_as_float(lo), __uint_as_float(hi));
}
__device__ __forceinline__ float sigm(float x) { return 1.0f / (1.0f + expf(-x)); }

// ---------------------------------------------------------------------------
__global__ void k_vv(const float* __restrict__ prior, const float* __restrict__ W1,
                     const float* __restrict__ b1, const float* __restrict__ W2,
                     const float* __restrict__ b2) {
    __shared__ float hid[NHID];
    int n = blockIdx.x, j = threadIdx.x;
    float acc = b1[j];
    const float* pr = prior + n * NP;
    #pragma unroll 8
    for (int p = 0; p < NP; ++p) acc = fmaf(pr[p], W1[p * NHID + j], acc);
    hid[j] = fmaxf(acc, 0.0f);
    __syncthreads();
    if (j < NE) {
        float a2 = b2[j];
        for (int k = 0; k < NHID; ++k) a2 = fmaf(hid[k], W2[k * NE + j], a2);
        g_vv[n * NE + j] = a2;
    }
}

__global__ void k_vt(const int* __restrict__ mask) {
    int tid = blockIdx.x * blockDim.x + threadIdx.x;
    if (tid >= NB * NN) return;
    int b = tid / NN, n = tid % NN;
    int s = 0;
    for (int t = 0; t < NT; ++t) s += mask[(b * NT + t) * NN + n];
    g_vt[tid] = (float)s;
}

// Active-batch bitmask per (n,t): bit b set iff mask[b,t,n]>0 and t < lengths[b]
__global__ void k_mask(const int* __restrict__ mask, const int* __restrict__ lengths) {
    int idx = blockIdx.x * blockDim.x + threadIdx.x;
    if (idx >= NN * NT) return;
    int n = idx % NN, t = idx / NN;
    unsigned w = 0;
    #pragma unroll 4
    for (int b = 0; b < NB; ++b)
        if (t < __ldg(&lengths[b]) && mask[(b * NT + t) * NN + n] > 0) w |= (1u << b);
    g_mb[n * NT + t] = w;
}

// ---------------------------------------------------------------------------
// Effective weights with COLUMN PERMUTATION:
//   pcol < 256:  pcol = 4*p + s,  s>>1 = gate (0=r,1=u), o = 2*p + (s&1)
//   pcol >= 256: gate c, o = pcol-256
// Row k<129 -> Wx (x part: obs rows 0..127, rarity row 128); k>=129 -> Wh.
// ---------------------------------------------------------------------------
__global__ void k_weff(const float* __restrict__ Wr, const float* __restrict__ Wu,
                       const float* __restrict__ Wc,
                       const float* __restrict__ br, const float* __restrict__ bu,
                       const float* __restrict__ bc) {
    int idx = blockIdx.x * blockDim.x + threadIdx.x;
    const int total = NN * 257 * NC;
    if (idx >= total) return;
    int pcol = idx % NC;
    int k    = (idx / NC) % 257;
    int n    = idx / (NC * 257);
    int g, o;
    if (pcol >= 256) { g = 2; o = pcol - 256; }
    else { g = (pcol >> 1) & 1; o = ((pcol >> 2) << 1) | (pcol & 1); }
    const float* W = (g == 0) ? Wr : ((g == 1) ? Wu : Wc);
    const float* vv = g_vv + n * NE;
    float acc = 0.0f;
    #pragma unroll
    for (int e = 0; e < NE; ++e)
        acc = fmaf(vv[e], W[(e * 257 + k) * ND + o], acc);
    if (k < 129) g_Wx[(n * 129 + k) * NC + pcol] = acc;
    else         g_Wh[(n * 128 + (k - 129)) * NC + pcol] = acc;
    if (k == 0) {
        const float* bb = (g == 0) ? br : ((g == 1) ? bu : bc);
        float ab = 0.0f;
        #pragma unroll
        for (int e = 0; e < NE; ++e) ab = fmaf(vv[e], bb[e * ND + o], ab);
        g_beff[n * NC + pcol] = ab;
    }
}

// ---------------------------------------------------------------------------
// gx[n,b,t,:] = [obs, rarity] @ Wx[n] + beff[n]   (permuted cols, t < lengths[b])
// ---------------------------------------------------------------------------
__global__ void __launch_bounds__(384) k_gx(const float* __restrict__ obs,
                                            const float* __restrict__ avg,
                                            const int* __restrict__ lengths) {
    const int b = blockIdx.x, n = blockIdx.y;
    const int tid = threadIdx.x;
    const int cg = tid % 96;
    const int rg = tid / 96;
    const int c4 = cg * 4;
    const int end = lengths[b] - 1;
    const float vt1 = g_vt[b * NN + n] + 1.0f;
    const float* Wx = g_Wx + n * (129 * NC);
    __shared__ u64 xs2[32][132];

    u64 bias0, bias1;
    { ulonglong2 bv = *(const ulonglong2*)(g_beff + n * NC + c4);
      bias0 = bv.x; bias1 = bv.y; }

    for (int t0 = 0; t0 <= end; t0 += 32) {
        const int rows = min(32, end + 1 - t0);
        __syncthreads();
        for (int i = tid; i < (rows << 7); i += 384) {
            int r = i >> 7, c = i & 127;
            xs2[r][c] = pk2(obs[(((b * NT + t0 + r) * NN) + n) * ND + c]);
        }
        if (tid < rows)
            xs2[tid][128] = pk2(0.5f * tanhf(avg[(b * NT + t0 + tid) * NN + n] / vt1));
        __syncthreads();

        u64 acc[8][2];
        #pragma unroll
        for (int r = 0; r < 8; ++r) { acc[r][0] = bias0; acc[r][1] = bias1; }

        #pragma unroll 1
        for (int k = 0; k < 129; ++k) {
            ulonglong2 w = *(const ulonglong2*)(Wx + k * NC + c4);
            #pragma unroll
            for (int r = 0; r < 8; ++r) {
                u64 xv = xs2[rg * 8 + r][k];
                fma2(acc[r][0], xv, w.x);
                fma2(acc[r][1], xv, w.y);
            }
        }
        #pragma unroll
        for (int r = 0; r < 8; ++r) {
            int row = rg * 8 + r;
            if (row < rows) {
                ulonglong2 st; st.x = acc[r][0]; st.y = acc[r][1];
                *(ulonglong2*)(g_gx + (((size_t)(n * NB + b) * NT) + t0 + row) * NC + c4) = st;
            }
        }
    }
}

// ---------------------------------------------------------------------------
// Scan step body. Weights come from SMEM (Whs), h from duplicated smem mirror.
// thread = (group g in 0..3, col-pair ct in 0..63); owns cols (2ct,2ct+1).
// ---------------------------------------------------------------------------
template<int NBQ>
__device__ __forceinline__ void scan_step(const float* __restrict__ Whs,
                                          const float* __restrict__ gx_nt,
                                          u64* __restrict__ h2s,
                                          const int* __restrict__ s_act,
                                          int cnt, int g, int ct)
{
    int nbr = (cnt - g + 3) >> 2; if (nbr > NBQ) nbr = NBQ;
    const int nb = nbr;
    int bofs[NBQ];
    const float* gp[NBQ];
    #pragma unroll
    for (int i = 0; i < NBQ; ++i) {
        int b = s_act[(i < nb) ? (g + 4 * i) : g];   // pad slots alias slot 0
        bofs[i] = b << 7;
        gp[i] = gx_nt + (size_t)b * (NT * NC);
    }

    // ---- phase 1: r,u gates ----
    u64 ar[NBQ], au[NBQ];
    #pragma unroll
    for (int i = 0; i < NBQ; ++i) {
        ulonglong2 gv = *(const ulonglong2*)(gp[i] + 4 * ct);
        ar[i] = gv.x; au[i] = gv.y;
    }
    const float* wb = Whs + 4 * ct;
    #pragma unroll 2
    for (int k = 0; k < 128; k += 2) {
        ulonglong2 w0 = *(const ulonglong2*)(wb + k * NC);
        ulonglong2 w1 = *(const ulonglong2*)(wb + (k + 1) * NC);
        #pragma unroll
        for (int i = 0; i < NBQ; ++i) {
            ulonglong2 hv = *(const ulonglong2*)(h2s + bofs[i] + k);
            fma2(ar[i], hv.x, w0.x); fma2(au[i], hv.x, w0.y);
            fma2(ar[i], hv.y, w1.x); fma2(au[i], hv.y, w1.y);
        }
    }
    float hr0[NBQ], hr1[NBQ], uu0[NBQ], uu1[NBQ];
    #pragma unroll
    for (int i = 0; i < NBQ; ++i) {
        float2 a = up2(ar[i]), uv = up2(au[i]);
        float r0 = sigm(a.x), r1 = sigm(a.y);
        uu0[i] = sigm(uv.x); uu1[i] = sigm(uv.y);
        float h0 = ((const float*)(h2s + bofs[i] + 2 * ct))[0];
        float h1 = ((const float*)(h2s + bofs[i] + 2 * ct + 1))[0];
        hr0[i] = r0 * h0; hr1[i] = r1 * h1;
    }
    __syncthreads();                       // all phase-1 h reads done
    #pragma unroll
    for (int i = 0; i < NBQ; ++i) if (i < nb) {
        h2s[bofs[i] + 2 * ct]     = pk2(hr0[i]);
        h2s[bofs[i] + 2 * ct + 1] = pk2(hr1[i]);
    }
    __syncthreads();                       // h_reset visible

    // ---- phase 2: c gate ----
    u64 ac[NBQ];
    #pragma unroll
    for (int i = 0; i < NBQ; ++i)
        ac[i] = *(const u64*)(gp[i] + 256 + 2 * ct);
    const float* wc = Whs + 256 + 2 * ct;
    #pragma unroll 2
    for (int k = 0; k < 128; k += 2) {
        u64 w0 = *(const u64*)(wc + k * NC);
        u64 w1 = *(const u64*)(wc + (k + 1) * NC);
        #pragma unroll
        for (int i = 0; i < NBQ; ++i) {
            ulonglong2 hv = *(const ulonglong2*)(h2s + bofs[i] + k);
            fma2(ac[i], hv.x, w0);
            fma2(ac[i], hv.y, w1);
        }
    }
    __syncthreads();                       // all phase-2 h_reset reads done
    #pragma unroll
    for (int i = 0; i < NBQ; ++i) if (i < nb) {
        float2 c = up2(ac[i]);
        float c0 = tanhf(c.x), c1 = tanhf(c.y);
        float h0 = fmaf(uu0[i], c0 - hr0[i], hr0[i]);
        float h1 = fmaf(uu1[i], c1 - hr1[i], hr1[i]);
        h2s[bofs[i] + 2 * ct]     = pk2(h0);
        h2s[bofs[i] + 2 * ct + 1] = pk2(h1);
    }
}

__global__ void __launch_bounds__(256) k_scan(const int* __restrict__ lengths,
                                              float* __restrict__ out) {
    const int n   = blockIdx.x;
    const int tid = threadIdx.x;
    const int g   = tid >> 6;
    const int ct  = tid & 63;
    extern __shared__ float dyn[];
    float* Whs = dyn;                         // 196608 B: node weights (smem-resident)
    u64*   h2s = (u64*)(dyn + WH_FLOATS);     // 32768 B: duplicated h
    __shared__ int s_act[NB];
    __shared__ int s_tmax;

    // Copy this node's Wh into smem (one-time) and init h.
    {
        const float4* src = (const float4*)(g_Wh + (size_t)n * WH_FLOATS);
        float4* dst = (float4*)Whs;
        #pragma unroll 4
        for (int j = tid; j < WH_FLOATS / 4; j += 256) dst[j] = src[j];
    }
    for (int j = tid; j < NB * 128; j += 256) h2s[j] = 0ull;
    if (tid == 0) {
        int m = 0;
        for (int b = 0; b < NB; ++b) { int e = lengths[b] - 1; if (e > m) m = e; }
        s_tmax = m;
    }
    __syncthreads();
    const int tmax = s_tmax;

    const float* gxn = g_gx + (size_t)n * NB * NT * NC;
    const unsigned* mw = g_mb + n * NT;

    for (int t = 0; t <= tmax; ++t) {
        unsigned word = mw[t];
        if (word == 0) continue;
        __syncthreads();                   // prior h writes / s_act uses done
        if (tid < 32 && ((word >> tid) & 1u))
            s_act[__popc(word & ((1u << tid) - 1u))] = tid;
        __syncthreads();
        int cnt = __popc(word);
        const float* gx_nt = gxn + (size_t)t * NC;
        switch ((cnt + 3) >> 2) {
            case 1: scan_step<1>(Whs, gx_nt, h2s, s_act, cnt, g, ct); break;
            case 2: scan_step<2>(Whs, gx_nt, h2s, s_act, cnt, g, ct); break;
            case 3: scan_step<3>(Whs, gx_nt, h2s, s_act, cnt, g, ct); break;
            case 4: scan_step<4>(Whs, gx_nt, h2s, s_act, cnt, g, ct); break;
            case 5: scan_step<5>(Whs, gx_nt, h2s, s_act, cnt, g, ct); break;
            case 6: scan_step<6>(Whs, gx_nt, h2s, s_act, cnt, g, ct); break;
            case 7: scan_step<7>(Whs, gx_nt, h2s, s_act, cnt, g, ct); break;
            default: scan_step<8>(Whs, gx_nt, h2s, s_act, cnt, g, ct); break;
        }
    }
    __syncthreads();
    // h[b] is frozen after t=end[b]; write all outputs once.
    for (int j = tid; j < NB * 128; j += 256) {
        int b = j >> 7, col = j & 127;
        out[((size_t)b * NN + n) * ND + col] = ((const float*)(h2s + j))[0];
    }
}

// ---------------------------------------------------------------------------
extern "C" void kernel_launch(void* const* d_in, const int* in_sizes, int n_in,
                              void* d_out, int out_size) {
    const float* obs   = (const float*)d_in[0];
    const int*   msk   = (const int*)d_in[2];
    const int*   lens  = (const int*)d_in[5];
    const float* avg   = (const float*)d_in[6];
    const float* prior = (const float*)d_in[7];
    const float* Wr = (const float*)d_in[8];
    const float* br = (const float*)d_in[9];
    const float* Wu = (const float*)d_in[10];
    const float* bu = (const float*)d_in[11];
    const float* Wc = (const float*)d_in[12];
    const float* bc = (const float*)d_in[13];
    const float* W1 = (const float*)d_in[14];
    const float* b1 = (const float*)d_in[15];
    const float* W2 = (const float*)d_in[16];
    const float* b2 = (const float*)d_in[17];
    float* out = (float*)d_out;

    static int s_attr_done = 0;
    if (!s_attr_done) {
        cudaFuncSetAttribute(k_scan, cudaFuncAttributeMaxDynamicSharedMemorySize, SCAN_SMEM);
        s_attr_done = 1;
    }

    k_vv<<<NN, NHID>>>(prior, W1, b1, W2, b2);
    k_vt<<<(NB * NN + 255) / 256, 256>>>(msk);
    k_mask<<<(NN * NT + 255) / 256, 256>>>(msk, lens);
    k_weff<<<(NN * 257 * NC + 255) / 256, 256>>>(Wr, Wu, Wc, br, bu, bc);
    k_gx<<<dim3(NB, NN), 384>>>(obs, avg, lens);
    k_scan<<<NN, 256, SCAN_SMEM>>>(lens, out);
}

// round 7
// speedup vs baseline: 5.7597x; 1.3641x over previous
#include <cuda_runtime.h>

#define NB 32    // batch
#define NT 256   // time steps
#define NN 100   // nodes
#define ND 128   // feature dim D
#define NE 5     // experts
#define NP 768   // prior emb dim
#define NHID 256 // prior MLP hidden
#define NC 384   // 3 gates * 128 output cols, interleaved: [ (r0,r1,u0,u1) x64 | c0..c127 ]

#define WH_FLOATS (128 * NC)               // 49152 floats = 196608 B
#define SCAN_SMEM (WH_FLOATS * 4 + NB * 128 * 8)  // 196608 + 32768 = 229376 B

typedef unsigned long long u64;
typedef unsigned short u16;

// -------- static device scratch --------
__device__ float g_vv[NN * NE];
__device__ float g_vt[NB * NN];
__device__ float g_beff[NN * NC];            // permuted cols
__device__ float g_Wx[NN * 129 * NC];        // permuted cols
__device__ float g_Wh[NN * 128 * NC];        // permuted cols
__device__ float g_gx[(size_t)NN * NB * NT * NC];    // chain-indexed x-contribs
__device__ u16 g_tl[NN * NB * NT];           // per-(n,b) list of active timesteps
__device__ int g_L[NN * NB];                 // chain lengths
__device__ unsigned g_cw[NN * NT];           // per-(n,j) active-batch bitmask (chain idx)

// -------- packed f32x2 helpers --------
__device__ __forceinline__ u64 pk2(float v) {
    u64 r; unsigned u = __float_as_uint(v);
    asm("mov.b64 %0, {%1, %1};" : "=l"(r) : "r"(u));
    return r;
}
__device__ __forceinline__ void fma2(u64& d, u64 a, u64 b) {
    asm("fma.rn.f32x2 %0, %1, %2, %0;" : "+l"(d) : "l"(a), "l"(b));
}
__device__ __forceinline__ float2 up2(u64 p) {
    unsigned lo, hi;
    asm("mov.b64 {%0, %1}, %2;" : "=r"(lo), "=r"(hi) : "l"(p));
    return make_float2(__uint_as_float(lo), __uint_as_float(hi));
}
__device__ __forceinline__ float sigm(float x) { return 1.0f / (1.0f + expf(-x)); }

// ---------------------------------------------------------------------------
__global__ void k_vv(const float* __restrict__ prior, const float* __restrict__ W1,
                     const float* __restrict__ b1, const float* __restrict__ W2,
                     const float* __restrict__ b2) {
    __shared__ float hid[NHID];
    int n = blockIdx.x, j = threadIdx.x;
    float acc = b1[j];
    const float* pr = prior + n * NP;
    #pragma unroll 8
    for (int p = 0; p < NP; ++p) acc = fmaf(pr[p], W1[p * NHID + j], acc);
    hid[j] = fmaxf(acc, 0.0f);
    __syncthreads();
    if (j < NE) {
        float a2 = b2[j];
        for (int k = 0; k < NHID; ++k) a2 = fmaf(hid[k], W2[k * NE + j], a2);
        g_vv[n * NE + j] = a2;
    }
}

__global__ void k_vt(const int* __restrict__ mask) {
    int tid = blockIdx.x * blockDim.x + threadIdx.x;
    if (tid >= NB * NN) return;
    int b = tid / NN, n = tid % NN;
    int s = 0;
    for (int t = 0; t < NT; ++t) s += mask[(b * NT + t) * NN + n];
    g_vt[tid] = (float)s;
}

// Build per-(n,b) compacted chain of active timesteps.
__global__ void k_chain(const int* __restrict__ mask, const int* __restrict__ lengths) {
    int tid = blockIdx.x * blockDim.x + threadIdx.x;
    if (tid >= NN * NB) return;
    int n = tid % NN, b = tid / NN;
    int len = lengths[b];
    u16* tl = g_tl + (n * NB + b) * NT;
    int cnt = 0;
    for (int t = 0; t < len; ++t)
        if (mask[(b * NT + t) * NN + n] > 0) tl[cnt++] = (u16)t;
    g_L[n * NB + b] = cnt;
}

// Per-(n,j) active-batch word over chain index: bit b set iff L[n,b] > j
__global__ void k_cw(void) {
    int idx = blockIdx.x * blockDim.x + threadIdx.x;
    if (idx >= NN * NT) return;
    int n = idx / NT, j = idx % NT;
    unsigned w = 0;
    #pragma unroll 4
    for (int b = 0; b < NB; ++b)
        if (g_L[n * NB + b] > j) w |= (1u << b);
    g_cw[idx] = w;
}

// ---------------------------------------------------------------------------
// Effective weights with COLUMN PERMUTATION:
//   pcol < 256:  pcol = 4*p + s,  s>>1 = gate (0=r,1=u), o = 2*p + (s&1)
//   pcol >= 256: gate c, o = pcol-256
// Row k<129 -> Wx (x part: obs rows 0..127, rarity row 128); k>=129 -> Wh.
// ---------------------------------------------------------------------------
__global__ void k_weff(const float* __restrict__ Wr, const float* __restrict__ Wu,
                       const float* __restrict__ Wc,
                       const float* __restrict__ br, const float* __restrict__ bu,
                       const float* __restrict__ bc) {
    int idx = blockIdx.x * blockDim.x + threadIdx.x;
    const int total = NN * 257 * NC;
    if (idx >= total) return;
    int pcol = idx % NC;
    int k    = (idx / NC) % 257;
    int n    = idx / (NC * 257);
    int g, o;
    if (pcol >= 256) { g = 2; o = pcol - 256; }
    else { g = (pcol >> 1) & 1; o = ((pcol >> 2) << 1) | (pcol & 1); }
    const float* W = (g == 0) ? Wr : ((g == 1) ? Wu : Wc);
    const float* vv = g_vv + n * NE;
    float acc = 0.0f;
    #pragma unroll
    for (int e = 0; e < NE; ++e)
        acc = fmaf(vv[e], W[(e * 257 + k) * ND + o], acc);
    if (k < 129) g_Wx[(n * 129 + k) * NC + pcol] = acc;
    else         g_Wh[(n * 128 + (k - 129)) * NC + pcol] = acc;
    if (k == 0) {
        const float* bb = (g == 0) ? br : ((g == 1) ? bu : bc);
        float ab = 0.0f;
        #pragma unroll
        for (int e = 0; e < NE; ++e) ab = fmaf(vv[e], bb[e * ND + o], ab);
        g_beff[n * NC + pcol] = ab;
    }
}

// ---------------------------------------------------------------------------
// gx[n,b,j,:] = [obs(b, tl[j], n), rarity] @ Wx[n] + beff[n]   for j < L[n,b]
// (chain-compacted: only ACTIVE steps are computed)
// ---------------------------------------------------------------------------
__global__ void __launch_bounds__(384) k_gx(const float* __restrict__ obs,
                                            const float* __restrict__ avg) {
    const int b = blockIdx.x, n = blockIdx.y;
    const int tid = threadIdx.x;
    const int cg = tid % 96;
    const int rg = tid / 96;
    const int c4 = cg * 4;
    const int L = g_L[n * NB + b];
    if (L == 0) return;
    const float vt1 = g_vt[b * NN + n] + 1.0f;
    const float* Wx = g_Wx + n * (129 * NC);
    const u16* tl = g_tl + (n * NB + b) * NT;
    __shared__ u64 xs2[32][132];
    __shared__ int s_t[32];

    u64 bias0, bias1;
    { ulonglong2 bv = *(const ulonglong2*)(g_beff + n * NC + c4);
      bias0 = bv.x; bias1 = bv.y; }

    for (int j0 = 0; j0 < L; j0 += 32) {
        const int rows = min(32, L - j0);
        __syncthreads();
        if (tid < rows) s_t[tid] = tl[j0 + tid];
        __syncthreads();
        for (int i = tid; i < (rows << 7); i += 384) {
            int r = i >> 7, c = i & 127;
            xs2[r][c] = pk2(obs[(((size_t)b * NT + s_t[r]) * NN + n) * ND + c]);
        }
        if (tid < rows)
            xs2[tid][128] = pk2(0.5f * tanhf(avg[((size_t)b * NT + s_t[tid]) * NN + n] / vt1));
        __syncthreads();

        u64 acc[8][2];
        #pragma unroll
        for (int r = 0; r < 8; ++r) { acc[r][0] = bias0; acc[r][1] = bias1; }

        #pragma unroll 1
        for (int k = 0; k < 129; ++k) {
            ulonglong2 w = *(const ulonglong2*)(Wx + k * NC + c4);
            #pragma unroll
            for (int r = 0; r < 8; ++r) {
                u64 xv = xs2[rg * 8 + r][k];
                fma2(acc[r][0], xv, w.x);
                fma2(acc[r][1], xv, w.y);
            }
        }
        #pragma unroll
        for (int r = 0; r < 8; ++r) {
            int row = rg * 8 + r;
            if (row < rows) {
                ulonglong2 st; st.x = acc[r][0]; st.y = acc[r][1];
                *(ulonglong2*)(g_gx + (((size_t)(n * NB + b) * NT) + j0 + row) * NC + c4) = st;
            }
        }
    }
}

// ---------------------------------------------------------------------------
// Scan step body. Weights from SMEM (Whs), h from duplicated smem mirror.
// thread = (group g in 0..3, col-pair ct in 0..63); owns cols (2ct,2ct+1).
// ---------------------------------------------------------------------------
template<int NBQ>
__device__ __forceinline__ void scan_step(const float* __restrict__ Whs,
                                          const float* __restrict__ gx_nt,
                                          u64* __restrict__ h2s,
                                          const int* __restrict__ s_act,
                                          int cnt, int g, int ct)
{
    int nbr = (cnt - g + 3) >> 2; if (nbr > NBQ) nbr = NBQ;
    const int nb = nbr;
    int bofs[NBQ];
    const float* gp[NBQ];
    #pragma unroll
    for (int i = 0; i < NBQ; ++i) {
        int b = s_act[(i < nb) ? (g + 4 * i) : g];   // pad slots alias slot 0
        bofs[i] = b << 7;
        gp[i] = gx_nt + (size_t)b * (NT * NC);
    }

    // ---- phase 1: r,u gates ----
    u64 ar[NBQ], au[NBQ];
    #pragma unroll
    for (int i = 0; i < NBQ; ++i) {
        ulonglong2 gv = *(const ulonglong2*)(gp[i] + 4 * ct);
        ar[i] = gv.x; au[i] = gv.y;
    }
    const float* wb = Whs + 4 * ct;
    #pragma unroll 2
    for (int k = 0; k < 128; k += 2) {
        ulonglong2 w0 = *(const ulonglong2*)(wb + k * NC);
        ulonglong2 w1 = *(const ulonglong2*)(wb + (k + 1) * NC);
        #pragma unroll
        for (int i = 0; i < NBQ; ++i) {
            ulonglong2 hv = *(const ulonglong2*)(h2s + bofs[i] + k);
            fma2(ar[i], hv.x, w0.x); fma2(au[i], hv.x, w0.y);
            fma2(ar[i], hv.y, w1.x); fma2(au[i], hv.y, w1.y);
        }
    }
    float hr0[NBQ], hr1[NBQ], uu0[NBQ], uu1[NBQ];
    #pragma unroll
    for (int i = 0; i < NBQ; ++i) {
        float2 a = up2(ar[i]), uv = up2(au[i]);
        float r0 = sigm(a.x), r1 = sigm(a.y);
        uu0[i] = sigm(uv.x); uu1[i] = sigm(uv.y);
        float h0 = ((const float*)(h2s + bofs[i] + 2 * ct))[0];
        float h1 = ((const float*)(h2s + bofs[i] + 2 * ct + 1))[0];
        hr0[i] = r0 * h0; hr1[i] = r1 * h1;
    }
    __syncthreads();                       // all phase-1 h reads done
    #pragma unroll
    for (int i = 0; i < NBQ; ++i) if (i < nb) {
        h2s[bofs[i] + 2 * ct]     = pk2(hr0[i]);
        h2s[bofs[i] + 2 * ct + 1] = pk2(hr1[i]);
    }
    __syncthreads();                       // h_reset visible

    // ---- phase 2: c gate ----
    u64 ac[NBQ];
    #pragma unroll
    for (int i = 0; i < NBQ; ++i)
        ac[i] = *(const u64*)(gp[i] + 256 + 2 * ct);
    const float* wc = Whs + 256 + 2 * ct;
    #pragma unroll 2
    for (int k = 0; k < 128; k += 2) {
        u64 w0 = *(const u64*)(wc + k * NC);
        u64 w1 = *(const u64*)(wc + (k + 1) * NC);
        #pragma unroll
        for (int i = 0; i < NBQ; ++i) {
            ulonglong2 hv = *(const ulonglong2*)(h2s + bofs[i] + k);
            fma2(ac[i], hv.x, w0);
            fma2(ac[i], hv.y, w1);
        }
    }
    __syncthreads();                       // all phase-2 h_reset reads done
    #pragma unroll
    for (int i = 0; i < NBQ; ++i) if (i < nb) {
        float2 c = up2(ac[i]);
        float c0 = tanhf(c.x), c1 = tanhf(c.y);
        float h0 = fmaf(uu0[i], c0 - hr0[i], hr0[i]);
        float h1 = fmaf(uu1[i], c1 - hr1[i], hr1[i]);
        h2s[bofs[i] + 2 * ct]     = pk2(h0);
        h2s[bofs[i] + 2 * ct + 1] = pk2(h1);
    }
}

__global__ void __launch_bounds__(256) k_scan(float* __restrict__ out) {
    const int n   = blockIdx.x;
    const int tid = threadIdx.x;
    const int g   = tid >> 6;
    const int ct  = tid & 63;
    extern __shared__ float dyn[];
    float* Whs = dyn;                         // 196608 B: node weights (smem-resident)
    u64*   h2s = (u64*)(dyn + WH_FLOATS);     // 32768 B: duplicated h
    __shared__ int s_act[NB];
    __shared__ int s_maxL;

    // Copy this node's Wh into smem (one-time) and init h.
    {
        const float4* src = (const float4*)(g_Wh + (size_t)n * WH_FLOATS);
        float4* dst = (float4*)Whs;
        #pragma unroll 4
        for (int j = tid; j < WH_FLOATS / 4; j += 256) dst[j] = src[j];
    }
    for (int j = tid; j < NB * 128; j += 256) h2s[j] = 0ull;
    if (tid < NB) s_act[tid] = 0;
    if (tid == 0) {
        int m = 0;
        for (int b = 0; b < NB; ++b) { int L = g_L[n * NB + b]; if (L > m) m = L; }
        s_maxL = m;
    }
    __syncthreads();
    const int maxL = s_maxL;

    const float* gxn = g_gx + (size_t)n * NB * NT * NC;
    const unsigned* cw = g_cw + n * NT;

    for (int j = 0; j < maxL; ++j) {
        unsigned word = cw[j];
        if (word == 0) continue;
        __syncthreads();                   // prior h writes / s_act uses done
        if (tid < 32 && ((word >> tid) & 1u))
            s_act[__popc(word & ((1u << tid) - 1u))] = tid;
        __syncthreads();
        int cnt = __popc(word);
        const float* gx_nt = gxn + (size_t)j * NC;
        switch ((cnt + 3) >> 2) {
            case 1: scan_step<1>(Whs, gx_nt, h2s, s_act, cnt, g, ct); break;
            case 2: scan_step<2>(Whs, gx_nt, h2s, s_act, cnt, g, ct); break;
            case 3: scan_step<3>(Whs, gx_nt, h2s, s_act, cnt, g, ct); break;
            case 4: scan_step<4>(Whs, gx_nt, h2s, s_act, cnt, g, ct); break;
            case 5: scan_step<5>(Whs, gx_nt, h2s, s_act, cnt, g, ct); break;
            case 6: scan_step<6>(Whs, gx_nt, h2s, s_act, cnt, g, ct); break;
            case 7: scan_step<7>(Whs, gx_nt, h2s, s_act, cnt, g, ct); break;
            default: scan_step<8>(Whs, gx_nt, h2s, s_act, cnt, g, ct); break;
        }
    }
    __syncthreads();
    // h[b] is frozen after its last active step; write all outputs once.
    for (int j = tid; j < NB * 128; j += 256) {
        int b = j >> 7, col = j & 127;
        out[((size_t)b * NN + n) * ND + col] = ((const float*)(h2s + j))[0];
    }
}

// ---------------------------------------------------------------------------
extern "C" void kernel_launch(void* const* d_in, const int* in_sizes, int n_in,
                              void* d_out, int out_size) {
    const float* obs   = (const float*)d_in[0];
    const int*   msk   = (const int*)d_in[2];
    const int*   lens  = (const int*)d_in[5];
    const float* avg   = (const float*)d_in[6];
    const float* prior = (const float*)d_in[7];
    const float* Wr = (const float*)d_in[8];
    const float* br = (const float*)d_in[9];
    const float* Wu = (const float*)d_in[10];
    const float* bu = (const float*)d_in[11];
    const float* Wc = (const float*)d_in[12];
    const float* bc = (const float*)d_in[13];
    const float* W1 = (const float*)d_in[14];
    const float* b1 = (const float*)d_in[15];
    const float* W2 = (const float*)d_in[16];
    const float* b2 = (const float*)d_in[17];
    float* out = (float*)d_out;

    static int s_attr_done = 0;
    if (!s_attr_done) {
        cudaFuncSetAttribute(k_scan, cudaFuncAttributeMaxDynamicSharedMemorySize, SCAN_SMEM);
        s_attr_done = 1;
    }

    k_vv<<<NN, NHID>>>(prior, W1, b1, W2, b2);
    k_vt<<<(NB * NN + 255) / 256, 256>>>(msk);
    k_chain<<<(NN * NB + 255) / 256, 256>>>(msk, lens);
    k_cw<<<(NN * NT + 255) / 256, 256>>>();
    k_weff<<<(NN * 257 * NC + 255) / 256, 256>>>(Wr, Wu, Wc, br, bu, bc);
    k_gx<<<dim3(NB, NN), 384>>>(obs, avg);
    k_scan<<<NN, 256, SCAN_SMEM>>>(out);
}

// round 8
// speedup vs baseline: 6.1666x; 1.0707x over previous
#include <cuda_runtime.h>

#define NB 32    // batch
#define NT 256   // time steps
#define NN 100   // nodes
#define ND 128   // feature dim D
#define NE 5     // experts
#define NP 768   // prior emb dim
#define NHID 256 // prior MLP hidden
#define NC 384   // 3 gates * 128 cols, interleaved: [ (r0,r1,u0,u1) x64 | c0..c127 ]

#define WH_FLOATS (128 * NC)                       // 196608 B
#define SCAN_SMEM (WH_FLOATS * 4 + NB * 128 * 8)   // 229376 B

typedef unsigned long long u64;
typedef unsigned short u16;

// -------- static device scratch --------
__device__ float g_vv[NN * NE];
__device__ float g_vt[NB * NN];
__device__ float g_beff[NN * NC];
__device__ float g_Wx[NN * 129 * NC];
__device__ float g_Wh[NN * 128 * NC];
__device__ float g_gx[(size_t)NN * NB * NT * NC];  // chain-indexed x-contribs
__device__ u16 g_tl[NN * NB * NT];                 // per-(n,b) active timestep list
__device__ int g_L[NN * NB];                       // chain lengths
__device__ int g_ord[NN * NB];                     // batch ids sorted by L desc
__device__ int g_Ls[NN * NB];                      // L values in sorted order

// -------- packed f32x2 helpers --------
__device__ __forceinline__ u64 pk2(float v) {
    u64 r; unsigned u = __float_as_uint(v);
    asm("mov.b64 %0, {%1, %1};" : "=l"(r) : "r"(u));
    return r;
}
__device__ __forceinline__ void fma2(u64& d, u64 a, u64 b) {
    asm("fma.rn.f32x2 %0, %1, %2, %0;" : "+l"(d) : "l"(a), "l"(b));
}
__device__ __forceinline__ float2 up2(u64 p) {
    unsigned lo, hi;
    asm("mov.b64 {%0, %1}, %2;" : "=r"(lo), "=r"(hi) : "l"(p));
    return make_float2(__uint_as_float(lo), __uint_as_float(hi));
}
__device__ __forceinline__ float sigm(float x) { return 1.0f / (1.0f + expf(-x)); }
#define GBAR(id) asm volatile("bar.sync %0, 64;" :: "r"(id) : "memory")

// ---------------------------------------------------------------------------
__global__ void k_vv(const float* __restrict__ prior, const float* __restrict__ W1,
                     const float* __restrict__ b1, const float* __restrict__ W2,
                     const float* __restrict__ b2) {
    __shared__ float hid[NHID];
    int n = blockIdx.x, j = threadIdx.x;
    float acc = b1[j];
    const float* pr = prior + n * NP;
    #pragma unroll 8
    for (int p = 0; p < NP; ++p) acc = fmaf(pr[p], W1[p * NHID + j], acc);
    hid[j] = fmaxf(acc, 0.0f);
    __syncthreads();
    if (j < NE) {
        float a2 = b2[j];
        for (int k = 0; k < NHID; ++k) a2 = fmaf(hid[k], W2[k * NE + j], a2);
        g_vv[n * NE + j] = a2;
    }
}

// var_total + chain build, fused (one thread per (n,b))
__global__ void k_prep(const int* __restrict__ mask, const int* __restrict__ lengths) {
    int tid = blockIdx.x * blockDim.x + threadIdx.x;
    if (tid >= NN * NB) return;
    int n = tid % NN, b = tid / NN;
    int len = lengths[b];
    u16* tl = g_tl + (n * NB + b) * NT;
    int cnt = 0, s = 0;
    for (int t = 0; t < NT; ++t) {
        int m = mask[(b * NT + t) * NN + n];
        s += m;
        if (t < len && m > 0) tl[cnt++] = (u16)t;
    }
    g_L[n * NB + b] = cnt;
    g_vt[b * NN + n] = (float)s;
}

// Sort batches per node by L descending (one warp per node).
__global__ void k_sort(void) {
    int n = blockIdx.x;
    int lane = threadIdx.x;
    int L = g_L[n * NB + lane];
    unsigned key = ((unsigned)L << 5) | (unsigned)lane;
    unsigned avail = 0xffffffffu;
    for (int r = 0; r < NB; ++r) {
        unsigned myk = ((avail >> lane) & 1u) ? key : 0u;
        unsigned mx = __reduce_max_sync(0xffffffffu, myk);
        int win = (int)(mx & 31u);
        if (lane == 0) {
            g_ord[n * NB + r] = win;
            g_Ls[n * NB + r] = (int)(mx >> 5);
        }
        avail &= ~(1u << win);
    }
}

// ---------------------------------------------------------------------------
// Effective weights with COLUMN PERMUTATION (same layout as before).
// ---------------------------------------------------------------------------
__global__ void k_weff(const float* __restrict__ Wr, const float* __restrict__ Wu,
                       const float* __restrict__ Wc,
                       const float* __restrict__ br, const float* __restrict__ bu,
                       const float* __restrict__ bc) {
    int idx = blockIdx.x * blockDim.x + threadIdx.x;
    const int total = NN * 257 * NC;
    if (idx >= total) return;
    int pcol = idx % NC;
    int k    = (idx / NC) % 257;
    int n    = idx / (NC * 257);
    int g, o;
    if (pcol >= 256) { g = 2; o = pcol - 256; }
    else { g = (pcol >> 1) & 1; o = ((pcol >> 2) << 1) | (pcol & 1); }
    const float* W = (g == 0) ? Wr : ((g == 1) ? Wu : Wc);
    const float* vv = g_vv + n * NE;
    float acc = 0.0f;
    #pragma unroll
    for (int e = 0; e < NE; ++e)
        acc = fmaf(vv[e], W[(e * 257 + k) * ND + o], acc);
    if (k < 129) g_Wx[(n * 129 + k) * NC + pcol] = acc;
    else         g_Wh[(n * 128 + (k - 129)) * NC + pcol] = acc;
    if (k == 0) {
        const float* bb = (g == 0) ? br : ((g == 1) ? bu : bc);
        float ab = 0.0f;
        #pragma unroll
        for (int e = 0; e < NE; ++e) ab = fmaf(vv[e], bb[e * ND + o], ab);
        g_beff[n * NC + pcol] = ab;
    }
}

// ---------------------------------------------------------------------------
// gx[n,b,j,:] = [obs(b, tl[j], n), rarity] @ Wx[n] + beff[n]   for j < L[n,b]
// ---------------------------------------------------------------------------
__global__ void __launch_bounds__(384) k_gx(const float* __restrict__ obs,
                                            const float* __restrict__ avg) {
    const int b = blockIdx.x, n = blockIdx.y;
    const int tid = threadIdx.x;
    const int cg = tid % 96;
    const int rg = tid / 96;
    const int c4 = cg * 4;
    const int L = g_L[n * NB + b];
    if (L == 0) return;
    const float vt1 = g_vt[b * NN + n] + 1.0f;
    const float* Wx = g_Wx + n * (129 * NC);
    const u16* tl = g_tl + (n * NB + b) * NT;
    __shared__ u64 xs2[32][132];
    __shared__ int s_t[32];

    u64 bias0, bias1;
    { ulonglong2 bv = *(const ulonglong2*)(g_beff + n * NC + c4);
      bias0 = bv.x; bias1 = bv.y; }

    for (int j0 = 0; j0 < L; j0 += 32) {
        const int rows = min(32, L - j0);
        __syncthreads();
        if (tid < rows) s_t[tid] = tl[j0 + tid];
        __syncthreads();
        for (int i = tid; i < (rows << 7); i += 384) {
            int r = i >> 7, c = i & 127;
            xs2[r][c] = pk2(obs[(((size_t)b * NT + s_t[r]) * NN + n) * ND + c]);
        }
        if (tid < rows)
            xs2[tid][128] = pk2(0.5f * tanhf(avg[((size_t)b * NT + s_t[tid]) * NN + n] / vt1));
        __syncthreads();

        u64 acc[8][2];
        #pragma unroll
        for (int r = 0; r < 8; ++r) { acc[r][0] = bias0; acc[r][1] = bias1; }

        #pragma unroll 1
        for (int k = 0; k < 129; ++k) {
            ulonglong2 w = *(const ulonglong2*)(Wx + k * NC + c4);
            #pragma unroll
            for (int r = 0; r < 8; ++r) {
                u64 xv = xs2[rg * 8 + r][k];
                fma2(acc[r][0], xv, w.x);
                fma2(acc[r][1], xv, w.y);
            }
        }
        #pragma unroll
        for (int r = 0; r < 8; ++r) {
            int row = rg * 8 + r;
            if (row < rows) {
                ulonglong2 st; st.x = acc[r][0]; st.y = acc[r][1];
                *(ulonglong2*)(g_gx + (((size_t)(n * NB + b) * NT) + j0 + row) * NC + c4) = st;
            }
        }
    }
}

// ---------------------------------------------------------------------------
// Per-group scan step: exactly NBQ active batches; per-group named barriers.
// thread = (group g, col-pair ct); owns r/u cols 4ct..4ct+3 and c cols 2ct,2ct+1.
// ---------------------------------------------------------------------------
template<int NBQ>
__device__ __forceinline__ void scan_step(const float* __restrict__ Whs,
                                          u64* __restrict__ h2s,
                                          const float* __restrict__ gxj,
                                          const int* __restrict__ bofs,
                                          const unsigned* __restrict__ goff,
                                          int barid, int ct)
{
    // ---- phase 1: r,u gates ----
    u64 ar[NBQ], au[NBQ];
    #pragma unroll
    for (int i = 0; i < NBQ; ++i) {
        ulonglong2 gv = *(const ulonglong2*)(gxj + goff[i] + 4 * ct);
        ar[i] = gv.x; au[i] = gv.y;
    }
    const float* wb = Whs + 4 * ct;
    #pragma unroll 2
    for (int k = 0; k < 128; k += 2) {
        ulonglong2 w0 = *(const ulonglong2*)(wb + k * NC);
        ulonglong2 w1 = *(const ulonglong2*)(wb + (k + 1) * NC);
        #pragma unroll
        for (int i = 0; i < NBQ; ++i) {
            ulonglong2 hv = *(const ulonglong2*)(h2s + bofs[i] + k);
            fma2(ar[i], hv.x, w0.x); fma2(au[i], hv.x, w0.y);
            fma2(ar[i], hv.y, w1.x); fma2(au[i], hv.y, w1.y);
        }
    }
    float hr0[NBQ], hr1[NBQ], uu0[NBQ], uu1[NBQ];
    #pragma unroll
    for (int i = 0; i < NBQ; ++i) {
        float2 a = up2(ar[i]), uv = up2(au[i]);
        float r0 = sigm(a.x), r1 = sigm(a.y);
        uu0[i] = sigm(uv.x); uu1[i] = sigm(uv.y);
        float h0 = ((const float*)(h2s + bofs[i] + 2 * ct))[0];
        float h1 = ((const float*)(h2s + bofs[i] + 2 * ct + 1))[0];
        hr0[i] = r0 * h0; hr1[i] = r1 * h1;
    }
    GBAR(barid);                           // group phase-1 h reads done
    #pragma unroll
    for (int i = 0; i < NBQ; ++i) {
        h2s[bofs[i] + 2 * ct]     = pk2(hr0[i]);
        h2s[bofs[i] + 2 * ct + 1] = pk2(hr1[i]);
    }
    GBAR(barid);                           // h_reset visible within group

    // ---- phase 2: c gate ----
    u64 ac[NBQ];
    #pragma unroll
    for (int i = 0; i < NBQ; ++i)
        ac[i] = *(const u64*)(gxj + goff[i] + 256 + 2 * ct);
    const float* wc = Whs + 256 + 2 * ct;
    #pragma unroll 2
    for (int k = 0; k < 128; k += 2) {
        u64 w0 = *(const u64*)(wc + k * NC);
        u64 w1 = *(const u64*)(wc + (k + 1) * NC);
        #pragma unroll
        for (int i = 0; i < NBQ; ++i) {
            ulonglong2 hv = *(const ulonglong2*)(h2s + bofs[i] + k);
            fma2(ac[i], hv.x, w0);
            fma2(ac[i], hv.y, w1);
        }
    }
    GBAR(barid);                           // group phase-2 reads done
    #pragma unroll
    for (int i = 0; i < NBQ; ++i) {
        float2 c = up2(ac[i]);
        float c0 = tanhf(c.x), c1 = tanhf(c.y);
        float h0 = fmaf(uu0[i], c0 - hr0[i], hr0[i]);
        float h1 = fmaf(uu1[i], c1 - hr1[i], hr1[i]);
        h2s[bofs[i] + 2 * ct]     = pk2(h0);
        h2s[bofs[i] + 2 * ct + 1] = pk2(h1);
    }
}

__global__ void __launch_bounds__(256) k_scan(float* __restrict__ out) {
    const int n   = blockIdx.x;
    const int tid = threadIdx.x;
    const int g   = tid >> 6;
    const int ct  = tid & 63;
    const int barid = g + 1;
    extern __shared__ float dyn[];
    float* Whs = dyn;                         // 196608 B node weights
    u64*   h2s = (u64*)(dyn + WH_FLOATS);     // 32768 B duplicated h

    // One-time: Wh to smem, h = 0.
    {
        const float4* src = (const float4*)(g_Wh + (size_t)n * WH_FLOATS);
        float4* dst = (float4*)Whs;
        #pragma unroll 4
        for (int j = tid; j < WH_FLOATS / 4; j += 256) dst[j] = src[j];
    }
    for (int j = tid; j < NB * 128; j += 256) h2s[j] = 0ull;
    __syncthreads();

    // Group's batches: sorted ranks g, g+4, ..., g+28 (round-robin balance).
    int bid[8], Lg[8], bofs[8];
    unsigned goff[8];
    #pragma unroll
    for (int i = 0; i < 8; ++i) {
        int r = g + 4 * i;
        bid[i]  = g_ord[n * NB + r];
        Lg[i]   = g_Ls[n * NB + r];
        bofs[i] = bid[i] << 7;
        goff[i] = (unsigned)bid[i] * (NT * NC);
    }
    const int maxj = Lg[0];
    const float* gxn = g_gx + (size_t)n * NB * NT * NC;

    for (int j = 0; j < maxj; ++j) {
        int nb = 0;
        #pragma unroll
        for (int i = 0; i < 8; ++i) nb += (Lg[i] > j) ? 1 : 0;
        const float* gxj = gxn + (size_t)j * NC;
        switch (nb) {
            case 1: scan_step<1>(Whs, h2s, gxj, bofs, goff, barid, ct); break;
            case 2: scan_step<2>(Whs, h2s, gxj, bofs, goff, barid, ct); break;
            case 3: scan_step<3>(Whs, h2s, gxj, bofs, goff, barid, ct); break;
            case 4: scan_step<4>(Whs, h2s, gxj, bofs, goff, barid, ct); break;
            case 5: scan_step<5>(Whs, h2s, gxj, bofs, goff, barid, ct); break;
            case 6: scan_step<6>(Whs, h2s, gxj, bofs, goff, barid, ct); break;
            case 7: scan_step<7>(Whs, h2s, gxj, bofs, goff, barid, ct); break;
            default: scan_step<8>(Whs, h2s, gxj, bofs, goff, barid, ct); break;
        }
    }

    // Each thread wrote its own cols of its group's batches; write them out.
    #pragma unroll
    for (int i = 0; i < 8; ++i) {
        float2 v;
        v.x = ((const float*)(h2s + bofs[i] + 2 * ct))[0];
        v.y = ((const float*)(h2s + bofs[i] + 2 * ct + 1))[0];
        *(float2*)(out + ((size_t)bid[i] * NN + n) * ND + 2 * ct) = v;
    }
}

// ---------------------------------------------------------------------------
extern "C" void kernel_launch(void* const* d_in, const int* in_sizes, int n_in,
                              void* d_out, int out_size) {
    const float* obs   = (const float*)d_in[0];
    const int*   msk   = (const int*)d_in[2];
    const int*   lens  = (const int*)d_in[5];
    const float* avg   = (const float*)d_in[6];
    const float* prior = (const float*)d_in[7];
    const float* Wr = (const float*)d_in[8];
    const float* br = (const float*)d_in[9];
    const float* Wu = (const float*)d_in[10];
    const float* bu = (const float*)d_in[11];
    const float* Wc = (const float*)d_in[12];
    const float* bc = (const float*)d_in[13];
    const float* W1 = (const float*)d_in[14];
    const float* b1 = (const float*)d_in[15];
    const float* W2 = (const float*)d_in[16];
    const float* b2 = (const float*)d_in[17];
    float* out = (float*)d_out;

    static int s_attr_done = 0;
    if (!s_attr_done) {
        cudaFuncSetAttribute(k_scan, cudaFuncAttributeMaxDynamicSharedMemorySize, SCAN_SMEM);
        s_attr_done = 1;
    }

    // Exactly 6 launches; k_scan is launch index 5 so ncu (-s 5 -c 1) captures it.
    k_vv<<<NN, NHID>>>(prior, W1, b1, W2, b2);
    k_prep<<<(NN * NB + 255) / 256, 256>>>(msk, lens);
    k_sort<<<NN, 32>>>();
    k_weff<<<(NN * 257 * NC + 255) / 256, 256>>>(Wr, Wu, Wc, br, bu, bc);
    k_gx<<<dim3(NB, NN), 384>>>(obs, avg);
    k_scan<<<NN, 256, SCAN_SMEM>>>(out);
}